// round 1
// baseline (speedup 1.0000x reference)
#include <cuda_runtime.h>

#define NB 16
#define NC 8
#define NS 128
#define NSTEPS 10
#define HB 16          // h rows per CTA (x NC channels = 128 threads)
#define DSP 129        // smem pitch (odd -> conflict-free both access patterns)

// Scratch (device globals: allocation-free rule)
static __device__ float g_u[NB*NC*NS*NS];                   // 8 MB ping state
static __device__ float g_inva[(NSTEPS+1)*NC*NS*NS];        // alpha sets t = m*dt, m=0..10
static __device__ float g_fa  [(NSTEPS+1)*NC*NS*NS];
static __device__ float g_invb[NSTEPS*NC*NS*NS];            // beta sets t = m*dt + dt/2
static __device__ float g_fb  [NSTEPS*NC*NS*NS];

// ---------------------------------------------------------------------------
// Precompute Thomas factors for every distinct coefficient set.
// a = c = -k ; b = 1+2k (1+k at ends); denom_i = b_i + k_i*f_{i-1} + EPS;
// inv_i = 1/denom_i ; f_i (=c_star_i) = -k_i * inv_i.
// ---------------------------------------------------------------------------
__global__ void k_precompute(const float* __restrict__ ab, const float* __restrict__ atc,
                             const float* __restrict__ bb, const float* __restrict__ btc)
{
    const int tid = blockIdx.x * blockDim.x + threadIdx.x;
    const int nA = (NSTEPS+1)*NC*NS;   // alpha rows (solve along w)
    const int nB = NSTEPS*NC*NS;       // beta columns (solve along h)

    if (tid < nA) {
        const int m  = tid / (NC*NS);
        const int ch = tid % (NC*NS);              // c*NS + h
        const float t = (float)((double)m * 0.001);
        const float* abp = ab  + (size_t)ch * NS;
        const float* atp = atc + (size_t)ch * NS;
        float* ip = g_inva + ((size_t)m*NC*NS + ch) * NS;
        float* fp = g_fa   + ((size_t)m*NC*NS + ch) * NS;
        float fprev = 0.f;
        #pragma unroll 4
        for (int w = 0; w < NS; w++) {
            float k = fminf(fmaxf(fmaf(atp[w], t, abp[w]), 1e-6f), 10.f) * 0.0005f; // *half/DX^2
            float bc = (w == 0 || w == NS-1) ? (1.f + k) : fmaf(2.f, k, 1.f);
            float denom = fmaf(k, fprev, bc) + 1e-6f;
            float inv = 1.f / denom;
            float f = -k * inv;
            ip[w] = inv; fp[w] = f; fprev = f;
        }
    } else if (tid < nA + nB) {
        const int id = tid - nA;
        const int m  = id / (NC*NS);
        const int cw = id % (NC*NS);
        const int c  = cw / NS, w = cw % NS;
        const float t = (float)((double)m * 0.001 + 0.0005);
        const size_t sbase = ((size_t)m*NC + c) * NS*NS + w;
        const size_t gbase = (size_t)c * NS*NS + w;
        float fprev = 0.f;
        #pragma unroll 4
        for (int h = 0; h < NS; h++) {
            const size_t gi = gbase + (size_t)h * NS;
            float k = fminf(fmaxf(fmaf(btc[gi], t, bb[gi]), 1e-6f), 10.f) * 0.001f;  // *DT/DY^2
            float bc = (h == 0 || h == NS-1) ? (1.f + k) : fmaf(2.f, k, 1.f);
            float denom = fmaf(k, fprev, bc) + 1e-6f;
            float inv = 1.f / denom;
            float f = -k * inv;
            g_invb[sbase + (size_t)h*NS] = inv;
            g_fb  [sbase + (size_t)h*NS] = f;
            fprev = f;
        }
    }
}

// backward substitution, in place on the thread's smem row
static __device__ __forceinline__ void x_backward_inplace(float* dsr, const float4* __restrict__ f4)
{
    float x = dsr[NS-1];
    {
        const float4 ff = f4[31];
        x = fmaf(-ff.z, x, dsr[126]); dsr[126] = x;
        x = fmaf(-ff.y, x, dsr[125]); dsr[125] = x;
        x = fmaf(-ff.x, x, dsr[124]); dsr[124] = x;
    }
    #pragma unroll 4
    for (int g = 30; g >= 0; g--) {
        const float4 ff = f4[g];
        x = fmaf(-ff.w, x, dsr[g*4+3]); dsr[g*4+3] = x;
        x = fmaf(-ff.z, x, dsr[g*4+2]); dsr[g*4+2] = x;
        x = fmaf(-ff.y, x, dsr[g*4+1]); dsr[g*4+1] = x;
        x = fmaf(-ff.x, x, dsr[g*4+0]); dsr[g*4+0] = x;
    }
}

// ---------------------------------------------------------------------------
// X-direction kernel. CTA = (b, h-block of 16) x all 8 channels, 128 threads.
// Thread r = hh*8 + c  ->  every 8-lane shuffle group holds all 8 channels,
// so channel mixing is pure register shuffles.
// MODE 0 (head):  mix(from usrc) + X(set)            -> g_u
// MODE 1 (body):  X(set) + mix + X(set)  (in-place)  -> g_u
// MODE 2 (tail):  X(set)                             -> udst (d_out)
// ---------------------------------------------------------------------------
template<int MODE>
__global__ void __launch_bounds__(128) k_xsweep(const float* __restrict__ usrc,
                                                float* __restrict__ udst,
                                                const float* __restrict__ cmg,
                                                int set)
{
    extern __shared__ float ds[];      // [128][DSP]
    const int r  = threadIdx.x;
    const int c  = r & 7;
    const int b  = blockIdx.x >> 3;
    const int hb = blockIdx.x & 7;
    const int h  = hb*HB + (r >> 3);
    float* dsr = ds + r * DSP;

    const size_t urow = (((size_t)b*NC + c)*NS + h) * (size_t)NS;
    const size_t crow = (((size_t)set*NC + c)*NS + h) * (size_t)NS;
    const float4* iv4 = (const float4*)(g_inva + crow);
    const float4* f4  = (const float4*)(g_fa   + crow);
    const unsigned FULL = 0xFFFFFFFFu;
    const int gb = (r & 31) & 24;      // base lane of this thread's 8-lane channel group

    float cmr[8];
    if (MODE != 2) {
        #pragma unroll
        for (int j = 0; j < 8; j++) cmr[j] = cmg[c*8 + j];
    }

    // ---- forward pass 1 ----
    {
        const float* src = (MODE == 0) ? usrc : (const float*)g_u;
        const float4* d4 = (const float4*)(src + urow);
        float dsp = 0.f;
        #pragma unroll 4
        for (int g = 0; g < NS/4; g++) {
            float4 dv = d4[g];
            if (MODE == 0) {        // channel mixing via warp shuffles
                float m0 = 0.f, m1 = 0.f, m2 = 0.f, m3 = 0.f;
                #pragma unroll
                for (int j = 0; j < 8; j++) {
                    const int sl = gb + j;
                    m0 = fmaf(cmr[j], __shfl_sync(FULL, dv.x, sl), m0);
                    m1 = fmaf(cmr[j], __shfl_sync(FULL, dv.y, sl), m1);
                    m2 = fmaf(cmr[j], __shfl_sync(FULL, dv.z, sl), m2);
                    m3 = fmaf(cmr[j], __shfl_sync(FULL, dv.w, sl), m3);
                }
                dv.x = m0; dv.y = m1; dv.z = m2; dv.w = m3;
            }
            const float4 iv = iv4[g];
            const float4 ff = f4[g];
            dsp = fmaf(-ff.x, dsp, dv.x*iv.x); dsr[g*4+0] = dsp;
            dsp = fmaf(-ff.y, dsp, dv.y*iv.y); dsr[g*4+1] = dsp;
            dsp = fmaf(-ff.z, dsp, dv.z*iv.z); dsr[g*4+2] = dsp;
            dsp = fmaf(-ff.w, dsp, dv.w*iv.w); dsr[g*4+3] = dsp;
        }
    }

    x_backward_inplace(dsr, f4);       // x values now sit in dsr

    if (MODE == 1) {
        // ---- mix + forward pass 2 (same alpha set) ----
        float dsp = 0.f;
        #pragma unroll 2
        for (int g = 0; g < NS/4; g++) {
            const float x0 = dsr[g*4+0], x1 = dsr[g*4+1];
            const float x2 = dsr[g*4+2], x3 = dsr[g*4+3];
            float m0 = 0.f, m1 = 0.f, m2 = 0.f, m3 = 0.f;
            #pragma unroll
            for (int j = 0; j < 8; j++) {
                const int sl = gb + j;
                m0 = fmaf(cmr[j], __shfl_sync(FULL, x0, sl), m0);
                m1 = fmaf(cmr[j], __shfl_sync(FULL, x1, sl), m1);
                m2 = fmaf(cmr[j], __shfl_sync(FULL, x2, sl), m2);
                m3 = fmaf(cmr[j], __shfl_sync(FULL, x3, sl), m3);
            }
            const float4 iv = iv4[g];
            const float4 ff = f4[g];
            dsp = fmaf(-ff.x, dsp, m0*iv.x); dsr[g*4+0] = dsp;
            dsp = fmaf(-ff.y, dsp, m1*iv.y); dsr[g*4+1] = dsp;
            dsp = fmaf(-ff.z, dsp, m2*iv.z); dsr[g*4+2] = dsp;
            dsp = fmaf(-ff.w, dsp, m3*iv.w); dsr[g*4+3] = dsp;
        }
        x_backward_inplace(dsr, f4);
    }

    // ---- coalesced transposed write-back ----
    __syncthreads();
    float* dst = (MODE == 2) ? udst : (float*)g_u;
    #pragma unroll 4
    for (int rr = 0; rr < 128; rr++) {
        const int cc  = rr & 7;
        const int hh2 = rr >> 3;
        const size_t row = (((size_t)b*NC + cc)*NS + (hb*HB + hh2)) * (size_t)NS;
        dst[row + threadIdx.x] = ds[rr*DSP + threadIdx.x];
    }
}

// ---------------------------------------------------------------------------
// Y-direction kernel. CTA = (b, c) slice, thread = column w. All global
// traffic is naturally coalesced; in-place on g_u (columns are independent).
// ---------------------------------------------------------------------------
__global__ void __launch_bounds__(128) k_ysweep(int set)
{
    extern __shared__ float ds[];      // [128 w][DSP]
    const int w = threadIdx.x;
    const int b = blockIdx.x >> 3;
    const int c = blockIdx.x & 7;
    float* dsr = ds + w * DSP;

    const size_t ub = (((size_t)b*NC + c)*NS) * (size_t)NS + w;
    const size_t cb = (((size_t)set*NC + c)*NS) * (size_t)NS + w;

    float dsp = 0.f;
    #pragma unroll 4
    for (int h = 0; h < NS; h++) {
        const float d  = g_u  [ub + (size_t)h*NS];
        const float iv = g_invb[cb + (size_t)h*NS];
        const float ff = g_fb  [cb + (size_t)h*NS];
        dsp = fmaf(-ff, dsp, d * iv);
        dsr[h] = dsp;
    }
    float x = dsr[NS-1];
    g_u[ub + (size_t)(NS-1)*NS] = x;
    #pragma unroll 4
    for (int h = NS-2; h >= 0; h--) {
        const float ff = g_fb[cb + (size_t)h*NS];
        x = fmaf(-ff, x, dsr[h]);
        g_u[ub + (size_t)h*NS] = x;
    }
}

// ---------------------------------------------------------------------------
// Inputs (metadata order): u, alpha_base, beta_base, alpha_time_coeff,
// beta_time_coeff, channel_mixing. Output: float32 [16,8,128,128].
// ---------------------------------------------------------------------------
extern "C" void kernel_launch(void* const* d_in, const int* in_sizes, int n_in,
                              void* d_out, int out_size)
{
    (void)in_sizes; (void)n_in; (void)out_size;
    const float* u   = (const float*)d_in[0];
    const float* ab  = (const float*)d_in[1];
    const float* bb  = (const float*)d_in[2];
    const float* atc = (const float*)d_in[3];
    const float* btc = (const float*)d_in[4];
    const float* cm  = (const float*)d_in[5];

    const int shmem = NS * DSP * (int)sizeof(float);   // 66048 B
    cudaFuncSetAttribute(k_xsweep<0>, cudaFuncAttributeMaxDynamicSharedMemorySize, shmem);
    cudaFuncSetAttribute(k_xsweep<1>, cudaFuncAttributeMaxDynamicSharedMemorySize, shmem);
    cudaFuncSetAttribute(k_xsweep<2>, cudaFuncAttributeMaxDynamicSharedMemorySize, shmem);
    cudaFuncSetAttribute(k_ysweep,    cudaFuncAttributeMaxDynamicSharedMemorySize, shmem);

    const int nPre = (NSTEPS+1)*NC*NS + NSTEPS*NC*NS;  // 21504 rows
    k_precompute<<<(nPre + 255) / 256, 256>>>(ab, atc, bb, btc);

    // step 0: mix + X(alpha set 0)
    k_xsweep<0><<<NB*(NS/HB), 128, shmem>>>(u, nullptr, cm, 0);

    for (int k = 0; k < NSTEPS; k++) {
        k_ysweep<<<NB*NC, 128, shmem>>>(k);                       // beta set k
        if (k < NSTEPS-1)
            k_xsweep<1><<<NB*(NS/HB), 128, shmem>>>(nullptr, nullptr, cm, k+1); // X + mix + X
        else
            k_xsweep<2><<<NB*(NS/HB), 128, shmem>>>(nullptr, (float*)d_out, cm, NSTEPS); // final X
    }
}

// round 2
// speedup vs baseline: 6.4014x; 6.4014x over previous
#include <cuda_runtime.h>

#define NB 16
#define NC 8
#define NS 128
#define NSTEPS 10
#define EPSF 1e-6f
#define FULLM 0xFFFFFFFFu
#define NITER 3

// ping state (device global: allocation-free rule)
static __device__ float g_u[NB*NC*NS*NS];

// ---------------------------------------------------------------------------
// In-register Neumann solve along w: y starts = d; 3x  y <- d - (K*L + eps)*y
// Warp owns a full row of 128; thread owns 4 consecutive elements.
// Mirror ghosts reproduce the b=1+k boundary rows exactly.
// ---------------------------------------------------------------------------
static __device__ __forceinline__ void xsolve(float y[4], const float d[4],
                                              const float k[4], int l)
{
    #pragma unroll
    for (int it = 0; it < NITER; it++) {
        float ym1 = __shfl_up_sync(FULLM, y[3], 1);
        float yp1 = __shfl_down_sync(FULLM, y[0], 1);
        if (l == 0)  ym1 = y[0];
        if (l == 31) yp1 = y[3];
        float prev = ym1;
        #pragma unroll
        for (int e = 0; e < 4; e++) {
            float cur = y[e];
            float nxt = (e < 3) ? y[e+1] : yp1;
            float L = 2.f*cur - prev - nxt;
            y[e] = d[e] - fmaf(k[e], L, EPSF*cur);
            prev = cur;
        }
    }
}

// ---------------------------------------------------------------------------
// X-direction kernel. CTA = (b, h); warp c handles channel c's row.
// MODE 0: mix(usrc) + X          -> g_u        (head, alpha @ t=0)
// MODE 1: X + mix + X (in place) -> g_u        (body, same alpha set twice)
// MODE 2: X                      -> uout       (tail, alpha @ t=10dt)
// ---------------------------------------------------------------------------
template<int MODE>
__global__ void __launch_bounds__(256) k_x(const float* __restrict__ usrc,
                                           float* __restrict__ uout,
                                           const float* __restrict__ ab,
                                           const float* __restrict__ atc,
                                           const float* __restrict__ cm,
                                           float t)
{
    __shared__ float sm[NC][NS];
    const int tid = threadIdx.x;
    const int c = tid >> 5;
    const int l = tid & 31;
    const int b = blockIdx.x >> 7;
    const int h = blockIdx.x & 127;

    const size_t crow = (((size_t)c*NS + h))*NS + 4*l;
    const size_t urow = ((((size_t)b*NC + c)*NS + h))*NS + 4*l;

    // coefficients: k = clip(ab + atc*t, eps, 10) * (dt/2)/dx^2
    float k[4];
    {
        const float4 a4 = *(const float4*)(ab + crow);
        const float4 c4 = *(const float4*)(atc + crow);
        k[0] = fminf(fmaxf(fmaf(c4.x, t, a4.x), 1e-6f), 10.f) * 0.0005f;
        k[1] = fminf(fmaxf(fmaf(c4.y, t, a4.y), 1e-6f), 10.f) * 0.0005f;
        k[2] = fminf(fmaxf(fmaf(c4.z, t, a4.z), 1e-6f), 10.f) * 0.0005f;
        k[3] = fminf(fmaxf(fmaf(c4.w, t, a4.w), 1e-6f), 10.f) * 0.0005f;
    }

    float cmr[8];
    if (MODE != 2) {
        #pragma unroll
        for (int j = 0; j < 8; j++) cmr[j] = cm[c*8 + j];
    }

    float d[4];
    {
        const float* src = (MODE == 0) ? usrc : (const float*)g_u;
        const float4 v = *(const float4*)(src + urow);
        d[0] = v.x; d[1] = v.y; d[2] = v.z; d[3] = v.w;
    }

    if (MODE == 0) {
        // channel mix first, then solve
        *(float4*)&sm[c][4*l] = make_float4(d[0], d[1], d[2], d[3]);
        __syncthreads();
        float m[4] = {0.f, 0.f, 0.f, 0.f};
        #pragma unroll
        for (int j = 0; j < 8; j++) {
            const float4 v = *(const float4*)&sm[j][4*l];
            m[0] = fmaf(cmr[j], v.x, m[0]);
            m[1] = fmaf(cmr[j], v.y, m[1]);
            m[2] = fmaf(cmr[j], v.z, m[2]);
            m[3] = fmaf(cmr[j], v.w, m[3]);
        }
        float y[4] = {m[0], m[1], m[2], m[3]};
        xsolve(y, m, k, l);
        *(float4*)((float*)g_u + urow) = make_float4(y[0], y[1], y[2], y[3]);
    } else if (MODE == 1) {
        float y[4] = {d[0], d[1], d[2], d[3]};
        xsolve(y, d, k, l);
        *(float4*)&sm[c][4*l] = make_float4(y[0], y[1], y[2], y[3]);
        __syncthreads();
        float m[4] = {0.f, 0.f, 0.f, 0.f};
        #pragma unroll
        for (int j = 0; j < 8; j++) {
            const float4 v = *(const float4*)&sm[j][4*l];
            m[0] = fmaf(cmr[j], v.x, m[0]);
            m[1] = fmaf(cmr[j], v.y, m[1]);
            m[2] = fmaf(cmr[j], v.z, m[2]);
            m[3] = fmaf(cmr[j], v.w, m[3]);
        }
        float y2[4] = {m[0], m[1], m[2], m[3]};
        xsolve(y2, m, k, l);
        *(float4*)((float*)g_u + urow) = make_float4(y2[0], y2[1], y2[2], y2[3]);
    } else {
        float y[4] = {d[0], d[1], d[2], d[3]};
        xsolve(y, d, k, l);
        *(float4*)(uout + urow) = make_float4(y[0], y[1], y[2], y[3]);
    }
}

// ---------------------------------------------------------------------------
// Y-direction kernel. CTA = (b, c, w-tile of 32); 128 threads as
// (32 w-lanes) x (4 h-segments). Thread owns 32 h in registers; segment
// halos exchanged via double-buffered smem rows. In place on g_u.
// ---------------------------------------------------------------------------
__global__ void __launch_bounds__(128) k_y(const float* __restrict__ bb,
                                           const float* __restrict__ btc,
                                           float t)
{
    __shared__ float sTop[2][4][32];
    __shared__ float sBot[2][4][32];
    const int wl = threadIdx.x & 31;
    const int s  = threadIdx.x >> 5;
    const int wt = blockIdx.x & 3;
    const int c  = (blockIdx.x >> 2) & 7;
    const int b  = blockIdx.x >> 5;
    const int w  = wt*32 + wl;
    const int h0 = s*32;

    const size_t cbase = (((size_t)c*NS + h0))*NS + w;
    const size_t ubase = ((((size_t)b*NC + c)*NS + h0))*NS + w;

    float k[32], d[32], y[32];
    #pragma unroll
    for (int j = 0; j < 32; j++) {
        const float base = bb [cbase + (size_t)j*NS];
        const float tc   = btc[cbase + (size_t)j*NS];
        k[j] = fminf(fmaxf(fmaf(tc, t, base), 1e-6f), 10.f) * 0.001f;  // *DT/DY^2
        d[j] = g_u[ubase + (size_t)j*NS];
        y[j] = d[j];
    }

    #pragma unroll
    for (int it = 0; it < NITER; it++) {
        const int buf = it & 1;
        sTop[buf][s][wl] = y[0];
        sBot[buf][s][wl] = y[31];
        __syncthreads();
        const float ym1 = (s == 0) ? y[0]  : sBot[buf][s-1][wl];
        const float yp1 = (s == 3) ? y[31] : sTop[buf][s+1][wl];
        float prev = ym1;
        #pragma unroll
        for (int j = 0; j < 32; j++) {
            const float cur = y[j];
            const float nxt = (j < 31) ? y[j+1] : yp1;
            const float L = 2.f*cur - prev - nxt;
            y[j] = d[j] - fmaf(k[j], L, EPSF*cur);
            prev = cur;
        }
    }

    #pragma unroll
    for (int j = 0; j < 32; j++)
        g_u[ubase + (size_t)j*NS] = y[j];
}

// ---------------------------------------------------------------------------
// Inputs (metadata order): u, alpha_base, beta_base, alpha_time_coeff,
// beta_time_coeff, channel_mixing. Output: float32 [16,8,128,128].
// ---------------------------------------------------------------------------
extern "C" void kernel_launch(void* const* d_in, const int* in_sizes, int n_in,
                              void* d_out, int out_size)
{
    (void)in_sizes; (void)n_in; (void)out_size;
    const float* u   = (const float*)d_in[0];
    const float* ab  = (const float*)d_in[1];
    const float* bb  = (const float*)d_in[2];
    const float* atc = (const float*)d_in[3];
    const float* btc = (const float*)d_in[4];
    const float* cm  = (const float*)d_in[5];

    // head: mix + X(alpha @ t=0)
    k_x<0><<<NB*NS, 256>>>(u, nullptr, ab, atc, cm, 0.f);

    for (int k = 0; k < NSTEPS; k++) {
        const float tB = (float)((double)k * 0.001 + 0.0005);
        k_y<<<NB*NC*4, 128>>>(bb, btc, tB);
        const float tA = (float)((double)(k+1) * 0.001);
        if (k < NSTEPS-1)
            k_x<1><<<NB*NS, 256>>>(nullptr, nullptr, ab, atc, cm, tA);     // X+mix+X
        else
            k_x<2><<<NB*NS, 256>>>(nullptr, (float*)d_out, ab, atc, cm, tA); // final X
    }
}